// round 13
// baseline (speedup 1.0000x reference)
#include <cuda_runtime.h>

// out[c] = sum_{i,j} w[i,j,c] * inputs[0,i,j,c];  H=W=512, C=256 (batch 0 only).
// R4 winning shape (persistent single wave, 4xLDG.128 batches) deepened to a
// 3-slot register pipeline: 2 batches perpetually in flight per warp.

#define NPOS   (512 * 512)
#define GRID   592                 // 148 SMs x 4 blocks: exactly one wave
#define UNITS  (NPOS / 8)          // work unit = 8 positions; 32768 units

__global__ void zero_out_kernel(float* out) { out[threadIdx.x] = 0.0f; }

__global__ __launch_bounds__(256, 4)
void chan_dot_kernel(const float4* __restrict__ in,
                     const float4* __restrict__ w,
                     float* __restrict__ out) {
    const int tx = threadIdx.x & 63;   // channel quad
    const int ty = threadIdx.x >> 6;   // 0..3 position sub-lane

    float ax = 0.f, ay = 0.f, az = 0.f, aw = 0.f;

    float4 a0[2], b0[2], a1[2], b1[2], a2[2], b2[2];

    // Unit u covers positions [8u, 8u+8); thread handles positions 8u+2*ty+{0,1}.
    // Warp reads 512B contiguous per position per stream -> fully coalesced.
    // Batch-granularity guard only (u < UNITS), loads inside are unconditional.
#define LOADB(A, B, u) do {                               \
        if ((u) < UNITS) {                                \
            const int _b = ((u) * 8 + ty * 2) * 64 + tx;  \
            A[0] = __ldcg(in + _b);                       \
            A[1] = __ldcg(in + _b + 64);                  \
            B[0] = __ldcg(w  + _b);                       \
            B[1] = __ldcg(w  + _b + 64);                  \
        }                                                 \
    } while (0)

#define FMAB(A, B) do {                                   \
        ax = fmaf(A[0].x, B[0].x, ax);                    \
        ay = fmaf(A[0].y, B[0].y, ay);                    \
        az = fmaf(A[0].z, B[0].z, az);                    \
        aw = fmaf(A[0].w, B[0].w, aw);                    \
        ax = fmaf(A[1].x, B[1].x, ax);                    \
        ay = fmaf(A[1].y, B[1].y, ay);                    \
        az = fmaf(A[1].z, B[1].z, az);                    \
        aw = fmaf(A[1].w, B[1].w, aw);                    \
    } while (0)

    const int bid  = blockIdx.x;
    const int mine = (UNITS - 1 - bid) / GRID + 1;   // 55 or 56 batches

    int u = bid;                       // batch k lives at unit bid + k*GRID
    LOADB(a0, b0, u);  u += GRID;      // slot 0 <- batch 0 (always valid)
    LOADB(a1, b1, u);  u += GRID;      // slot 1 <- batch 1 (guarded)

    // Steady state: load batch k+2, consume batch k. Two batches in flight.
    int k = 0;
    for (; k + 3 <= mine; k += 3) {
        LOADB(a2, b2, u);  u += GRID;  FMAB(a0, b0);
        LOADB(a0, b0, u);  u += GRID;  FMAB(a1, b1);
        LOADB(a1, b1, u);  u += GRID;  FMAB(a2, b2);
    }
    // Tail: r = mine - k in {1, 2}; slots 0/1 hold batches k / k+1.
    const int r = mine - k;
    if (r >= 1) FMAB(a0, b0);
    if (r >= 2) FMAB(a1, b1);

#undef LOADB
#undef FMAB

    // Reduce 4 position sub-lanes per channel quad via smem, then atomics.
    __shared__ float4 s[4][64];
    s[ty][tx] = make_float4(ax, ay, az, aw);
    __syncthreads();

    if (ty == 0) {
        const float4 t0 = s[0][tx];
        const float4 t1 = s[1][tx];
        const float4 t2 = s[2][tx];
        const float4 t3 = s[3][tx];
        atomicAdd(&out[tx * 4 + 0], (t0.x + t1.x) + (t2.x + t3.x));
        atomicAdd(&out[tx * 4 + 1], (t0.y + t1.y) + (t2.y + t3.y));
        atomicAdd(&out[tx * 4 + 2], (t0.z + t1.z) + (t2.z + t3.z));
        atomicAdd(&out[tx * 4 + 3], (t0.w + t1.w) + (t2.w + t3.w));
    }
}

extern "C" void kernel_launch(void* const* d_in, const int* in_sizes, int n_in,
                              void* d_out, int out_size) {
    const float4* in = (const float4*)d_in[0];   // (2,512,512,256) f32; batch 0 only
    const float4* w  = (const float4*)d_in[1];   // (512,512,256) f32
    float* out = (float*)d_out;                  // 256 f32

    zero_out_kernel<<<1, 256>>>(out);
    chan_dot_kernel<<<GRID, 256>>>(in, w, out);
}

// round 14
// speedup vs baseline: 1.0606x; 1.0606x over previous
#include <cuda_runtime.h>

// out[c] = sum_{i,j} w[i,j,c] * inputs[0,i,j,c];  H=W=512, C=256 (batch 0 only).
// R4 winning shape (2-deep register pipeline, 4xLDG.128 batches), occupancy
// raised 4->5 blocks/SM via lean running-index addressing (goal: regs <= 51).

#define NPOS    (512 * 512)
#define GRID    740                // 148 SMs x 5 blocks: exactly one wave
#define UNITS   (NPOS / 8)         // work unit = 8 positions; 32768 units
#define NF4     16777216           // f4 elements per stream
#define GSTRIDE (GRID * 512)       // f4 index stride per batch: 378880

__global__ void zero_out_kernel(float* out) { out[threadIdx.x] = 0.0f; }

__global__ __launch_bounds__(256, 5)
void chan_dot_kernel(const float4* __restrict__ in,
                     const float4* __restrict__ w,
                     float* __restrict__ out) {
    const int tx = threadIdx.x & 63;   // channel quad
    const int ty = threadIdx.x >> 6;   // 0..3 position sub-lane

    float ax = 0.f, ay = 0.f, az = 0.f, aw = 0.f;

    float4 a0[2], b0[2], a1[2], b1[2];

    // Batch k of block b = unit b + k*GRID; this thread's f4 index within
    // batch k is gi = (b + k*GRID)*512 + ty*128 + tx, advanced by GSTRIDE.
    // Guard gi < NF4 is uniform across the block (per-thread offset < 512).
#define LOADB(A, B, g) do {                               \
        A[0] = __ldcs(in + (g));                          \
        A[1] = __ldcs(in + (g) + 64);                     \
        B[0] = __ldcs(w  + (g));                          \
        B[1] = __ldcs(w  + (g) + 64);                     \
    } while (0)

#define FMAB(A, B) do {                                   \
        ax = fmaf(A[0].x, B[0].x, ax);                    \
        ay = fmaf(A[0].y, B[0].y, ay);                    \
        az = fmaf(A[0].z, B[0].z, az);                    \
        aw = fmaf(A[0].w, B[0].w, aw);                    \
        ax = fmaf(A[1].x, B[1].x, ax);                    \
        ay = fmaf(A[1].y, B[1].y, ay);                    \
        az = fmaf(A[1].z, B[1].z, az);                    \
        aw = fmaf(A[1].w, B[1].w, aw);                    \
    } while (0)

    int gi = blockIdx.x * 512 + ty * 128 + tx;   // batch 0 (always valid)
    LOADB(a0, b0, gi);
    gi += GSTRIDE;

    for (;;) {
        if (gi < NF4) {                           // batch k+1 in flight
            LOADB(a1, b1, gi);
            gi += GSTRIDE;
            FMAB(a0, b0);
        } else { FMAB(a0, b0); break; }

        if (gi < NF4) {                           // batch k+2 in flight
            LOADB(a0, b0, gi);
            gi += GSTRIDE;
            FMAB(a1, b1);
        } else { FMAB(a1, b1); break; }
    }

#undef LOADB
#undef FMAB

    // Reduce 4 position sub-lanes per channel quad via smem, then atomics.
    __shared__ float4 s[4][64];
    s[ty][tx] = make_float4(ax, ay, az, aw);
    __syncthreads();

    if (ty == 0) {
        const float4 t0 = s[0][tx];
        const float4 t1 = s[1][tx];
        const float4 t2 = s[2][tx];
        const float4 t3 = s[3][tx];
        atomicAdd(&out[tx * 4 + 0], (t0.x + t1.x) + (t2.x + t3.x));
        atomicAdd(&out[tx * 4 + 1], (t0.y + t1.y) + (t2.y + t3.y));
        atomicAdd(&out[tx * 4 + 2], (t0.z + t1.z) + (t2.z + t3.z));
        atomicAdd(&out[tx * 4 + 3], (t0.w + t1.w) + (t2.w + t3.w));
    }
}

extern "C" void kernel_launch(void* const* d_in, const int* in_sizes, int n_in,
                              void* d_out, int out_size) {
    const float4* in = (const float4*)d_in[0];   // (2,512,512,256) f32; batch 0 only
    const float4* w  = (const float4*)d_in[1];   // (512,512,256) f32
    float* out = (float*)d_out;                  // 256 f32

    zero_out_kernel<<<1, 256>>>(out);
    chan_dot_kernel<<<GRID, 256>>>(in, w, out);
}

// round 15
// speedup vs baseline: 1.2286x; 1.1584x over previous
#include <cuda_runtime.h>
#include <cstdint>

// out[c] = sum_{i,j} w[i,j,c] * inputs[0,i,j,c];  H=W=512, C=256 (batch 0 only).
// LDG variants plateau at ~5.5TB/s (SM-wide LDG queue cap). This uses the bulk
// async-copy engine instead: per-warp private 3-stage cp.async.bulk pipelines
// into SMEM (2KB/stream/stage), self-synchronized -> structurally hang-proof.

#define THREADS  256
#define WPB      8                  // warps per block
#define GRIDB    296                // 148 SMs x 2 blocks
#define KSTAGES  3
#define CHUNK    2048               // bytes per stream per warp-iteration
#define TOTW     (GRIDB * WPB)      // 2368 warps chip-wide
#define NCHUNKS  131072             // 256MB / 2KB per stream
#define DYNSMEM  (1024 + WPB * KSTAGES * 2 * CHUNK)   // 99328 B

__global__ void zero_out_kernel(float* out) { out[threadIdx.x] = 0.0f; }

__device__ __forceinline__ uint32_t smem_u32(const void* p) {
    return (uint32_t)__cvta_generic_to_shared(p);
}
__device__ __forceinline__ void mbar_init(uint32_t a, uint32_t cnt) {
    asm volatile("mbarrier.init.shared.b64 [%0], %1;" :: "r"(a), "r"(cnt) : "memory");
}
__device__ __forceinline__ void mbar_expect_tx(uint32_t a, uint32_t bytes) {
    asm volatile("mbarrier.arrive.expect_tx.shared.b64 _, [%0], %1;" :: "r"(a), "r"(bytes) : "memory");
}
__device__ __forceinline__ void mbar_wait(uint32_t a, uint32_t parity) {
    asm volatile(
        "{\n\t.reg .pred P;\n\t"
        "WAIT_%=:\n\t"
        "mbarrier.try_wait.parity.acquire.cta.shared::cta.b64 P, [%0], %1, 0x989680;\n\t"
        "@P bra.uni DONE_%=;\n\t"
        "bra.uni WAIT_%=;\n\t"
        "DONE_%=:\n\t}"
        :: "r"(a), "r"(parity) : "memory");
}
__device__ __forceinline__ void bulk_g2s(uint32_t dst, const void* src, uint32_t bytes, uint32_t mbar) {
    asm volatile(
        "cp.async.bulk.shared::cluster.global.mbarrier::complete_tx::bytes [%0], [%1], %2, [%3];"
        :: "r"(dst), "l"(src), "r"(bytes), "r"(mbar) : "memory");
}

extern __shared__ char dynsmem[];

__global__ __launch_bounds__(THREADS, 2)
void chan_dot_bulk(const char* __restrict__ in_bytes,
                   const char* __restrict__ w_bytes,
                   float* __restrict__ out)
{
    const int tid  = threadIdx.x;
    const int wid  = tid >> 5;
    const int lane = tid & 31;

    // smem: [0..192) mbarriers (8 warps x 3 stages x 8B), buffers at +1024.
    // Stage (w,s): A-tile at 1024 + (w*K+s)*4096, B-tile at +2048.
    const uint32_t mb0 = smem_u32(dynsmem);
    if (lane == 0) {
        #pragma unroll
        for (int s = 0; s < KSTAGES; s++)
            mbar_init(mb0 + (wid * KSTAGES + s) * 8, 1);
    }
    asm volatile("fence.mbarrier_init.release.cluster;" ::: "memory");
    __syncthreads();

    const int wg   = blockIdx.x * WPB + wid;                    // global warp id
    const int mine = (NCHUNKS - 1 - wg) / TOTW + 1;             // 55 or 56 chunks

#define MB(s)    (mb0 + (wid * KSTAGES + (s)) * 8)
#define ABUF(s)  (dynsmem + 1024 + (wid * KSTAGES + (s)) * 2 * CHUNK)
#define BBUF(s)  (ABUF(s) + CHUNK)

#define ISSUE(s, it) do {                                              \
        const size_t _off = ((size_t)wg + (size_t)(it) * TOTW) * CHUNK;\
        mbar_expect_tx(MB(s), 2 * CHUNK);                              \
        bulk_g2s(smem_u32(ABUF(s)), in_bytes + _off, CHUNK, MB(s));    \
        bulk_g2s(smem_u32(BBUF(s)), w_bytes  + _off, CHUNK, MB(s));    \
    } while (0)

    // Prologue: fill this warp's stages
    if (lane == 0) {
        #pragma unroll
        for (int s = 0; s < KSTAGES; s++)
            if (s < mine) ISSUE(s, s);
    }

    // Each chunk = 128 f4; lane handles f4 {lane, lane+32, lane+64, lane+96}.
    // Channel quad of f4 j is j&63 (chunk base is 128-f4 aligned):
    //   accA <- quad lane     (j = lane, lane+64)
    //   accB <- quad lane+32  (j = lane+32, lane+96)
    float4 accA = make_float4(0.f, 0.f, 0.f, 0.f);
    float4 accB = make_float4(0.f, 0.f, 0.f, 0.f);

    for (int it = 0; it < mine; it++) {
        const int s = it % KSTAGES;
        mbar_wait(MB(s), (uint32_t)((it / KSTAGES) & 1));

        const float4* A = (const float4*)ABUF(s);
        const float4* B = (const float4*)BBUF(s);
        const float4 a0 = A[lane],      b0 = B[lane];
        const float4 a1 = A[lane + 32], b1 = B[lane + 32];
        const float4 a2 = A[lane + 64], b2 = B[lane + 64];
        const float4 a3 = A[lane + 96], b3 = B[lane + 96];

        accA.x = fmaf(a0.x, b0.x, accA.x);  accA.y = fmaf(a0.y, b0.y, accA.y);
        accA.z = fmaf(a0.z, b0.z, accA.z);  accA.w = fmaf(a0.w, b0.w, accA.w);
        accB.x = fmaf(a1.x, b1.x, accB.x);  accB.y = fmaf(a1.y, b1.y, accB.y);
        accB.z = fmaf(a1.z, b1.z, accB.z);  accB.w = fmaf(a1.w, b1.w, accB.w);
        accA.x = fmaf(a2.x, b2.x, accA.x);  accA.y = fmaf(a2.y, b2.y, accA.y);
        accA.z = fmaf(a2.z, b2.z, accA.z);  accA.w = fmaf(a2.w, b2.w, accA.w);
        accB.x = fmaf(a3.x, b3.x, accB.x);  accB.y = fmaf(a3.y, b3.y, accB.y);
        accB.z = fmaf(a3.z, b3.z, accB.z);  accB.w = fmaf(a3.w, b3.w, accB.w);

        __syncwarp();                       // all lanes consumed stage s
        if (lane == 0) {
            const int nit = it + KSTAGES;
            if (nit < mine) ISSUE(s, nit);  // safe: whole warp is past stage s
        }
    }

#undef ISSUE
#undef MB
#undef ABUF
#undef BBUF

    // Block reduction over 8 warps, then atomics (296 adds per channel).
    __shared__ float4 redA[WPB][32];
    __shared__ float4 redB[WPB][32];
    redA[wid][lane] = accA;
    redB[wid][lane] = accB;
    __syncthreads();

    if (tid < 64) {
        const int q = tid;                  // channel quad 0..63
        float rx = 0.f, ry = 0.f, rz = 0.f, rw = 0.f;
        #pragma unroll
        for (int v = 0; v < WPB; v++) {
            const float4 t = (q < 32) ? redA[v][q] : redB[v][q - 32];
            rx += t.x; ry += t.y; rz += t.z; rw += t.w;
        }
        atomicAdd(&out[q * 4 + 0], rx);
        atomicAdd(&out[q * 4 + 1], ry);
        atomicAdd(&out[q * 4 + 2], rz);
        atomicAdd(&out[q * 4 + 3], rw);
    }
}

extern "C" void kernel_launch(void* const* d_in, const int* in_sizes, int n_in,
                              void* d_out, int out_size) {
    const char* in_bytes = (const char*)d_in[0];   // (2,512,512,256) f32; batch 0 = first 256MB
    const char* w_bytes  = (const char*)d_in[1];   // (512,512,256) f32 = 256MB
    float* out = (float*)d_out;                    // 256 f32

    cudaFuncSetAttribute(chan_dot_bulk, cudaFuncAttributeMaxDynamicSharedMemorySize, DYNSMEM);

    zero_out_kernel<<<1, 256>>>(out);
    chan_dot_bulk<<<GRIDB, THREADS, DYNSMEM>>>(in_bytes, w_bytes, out);
}